// round 17
// baseline (speedup 1.0000x reference)
#include <cuda_runtime.h>
#include <cuda_fp16.h>
#include <math.h>
#include <float.h>

#define N 4096
#define IN_F 256
#define H0 64
#define H1 64
#define H2 32
#define CAP 256
#define SLOPE 0.01f

// -------- scratch (device globals; no allocation) --------
__device__ int    g_nbr_idx[N * CAP];     // only the selected relation
__device__ int    g_nbr_cnt[N];
__device__ __half g_WhH[3 * N * H0];      // fp16 Wh (gather traffic halved)
__device__ float  g_ssrc[3 * N];
__device__ float  g_sdst[3 * N];
__device__ float  g_support[N * H1];
__device__ float  g_support2[N * H2];
__device__ float  g_resid[N * H2];
__device__ float2 g_WgC[H1 * H2];          // {Wg1[k][j], Wr[j][k]} combined

__device__ __forceinline__ float leaky(float v) { return v >= 0.f ? v : SLOPE * v; }

__device__ __forceinline__ int read_relation(const void* p) {
    int r = *reinterpret_cast<const int*>(p);
    if (r < 0 || r > 2) {
        float fv = *reinterpret_cast<const float*>(p);
        r = (int)fv;
        if (r < 0 || r > 2) r = 0;
    }
    return r;
}

__device__ __forceinline__ unsigned mask16(float4 v0, float4 v1, float4 v2, float4 v3) {
    unsigned mask = 0;
    if (v0.x > 0.f) mask |= 1u << 0;  if (v0.y > 0.f) mask |= 1u << 1;
    if (v0.z > 0.f) mask |= 1u << 2;  if (v0.w > 0.f) mask |= 1u << 3;
    if (v1.x > 0.f) mask |= 1u << 4;  if (v1.y > 0.f) mask |= 1u << 5;
    if (v1.z > 0.f) mask |= 1u << 6;  if (v1.w > 0.f) mask |= 1u << 7;
    if (v2.x > 0.f) mask |= 1u << 8;  if (v2.y > 0.f) mask |= 1u << 9;
    if (v2.z > 0.f) mask |= 1u << 10; if (v2.w > 0.f) mask |= 1u << 11;
    if (v3.x > 0.f) mask |= 1u << 12; if (v3.y > 0.f) mask |= 1u << 13;
    if (v3.z > 0.f) mask |= 1u << 14; if (v3.w > 0.f) mask |= 1u << 15;
    return mask;
}

// ====== kernel 1: Wh = x @ W_r, s_src, s_dst (+WgC prep), 32-row tiles ====
__global__ void __launch_bounds__(256)
wh_kernel(const float* __restrict__ x,
          const float* __restrict__ W1, const float* __restrict__ a1,
          const float* __restrict__ W2, const float* __restrict__ a2,
          const float* __restrict__ W3, const float* __restrict__ a3,
          const float* __restrict__ Wg1, const float* __restrict__ Wr) {
    int r = blockIdx.y;
    int row0 = blockIdx.x * 32;
    const float* W = (r == 0) ? W1 : (r == 1) ? W2 : W3;
    const float* a = (r == 0) ? a1 : (r == 1) ? a2 : a3;
    int tid = threadIdx.x;
    int rg = tid >> 4;    // 0..15, two rows each
    int cgp = tid & 15;

    if (blockIdx.x == 0 && r == 0) {
#pragma unroll
        for (int t = tid; t < H1 * H2; t += 256) {
            int k = t >> 5, j = t & 31;
            g_WgC[t] = make_float2(Wg1[k * H2 + j], Wr[j * H1 + k]);
        }
    }

    __shared__ float sx[32][64];
    __shared__ float sW[64][64];

    float4 acc[2];
    acc[0] = make_float4(0.f, 0.f, 0.f, 0.f);
    acc[1] = make_float4(0.f, 0.f, 0.f, 0.f);

    for (int k0 = 0; k0 < IN_F; k0 += 64) {
        __syncthreads();
#pragma unroll
        for (int q = 0; q < 2; q++) {
            int lin = tid + q * 256;
            int rr = lin >> 4, c4 = (lin & 15) << 2;
            *(float4*)&sx[rr][c4] = *(const float4*)(x + (size_t)(row0 + rr) * IN_F + k0 + c4);
        }
#pragma unroll
        for (int q = 0; q < 4; q++) {
            int lin = tid + q * 256;
            int kr = lin >> 4, c4 = (lin & 15) << 2;
            *(float4*)&sW[kr][c4] = *(const float4*)(W + (size_t)(k0 + kr) * H0 + c4);
        }
        __syncthreads();
#pragma unroll 16
        for (int kk = 0; kk < 64; kk++) {
            float4 wv = *(float4*)&sW[kk][cgp * 4];
            float xv0 = sx[rg * 2 + 0][kk];
            float xv1 = sx[rg * 2 + 1][kk];
            acc[0].x = fmaf(xv0, wv.x, acc[0].x); acc[0].y = fmaf(xv0, wv.y, acc[0].y);
            acc[0].z = fmaf(xv0, wv.z, acc[0].z); acc[0].w = fmaf(xv0, wv.w, acc[0].w);
            acc[1].x = fmaf(xv1, wv.x, acc[1].x); acc[1].y = fmaf(xv1, wv.y, acc[1].y);
            acc[1].z = fmaf(xv1, wv.z, acc[1].z); acc[1].w = fmaf(xv1, wv.w, acc[1].w);
        }
    }

    float4 av = *(const float4*)(a + cgp * 4);
    float4 ad = *(const float4*)(a + H0 + cgp * 4);
#pragma unroll
    for (int ri = 0; ri < 2; ri++) {
        int grow = row0 + rg * 2 + ri;
        __half2 h01 = __float22half2_rn(make_float2(acc[ri].x, acc[ri].y));
        __half2 h23 = __float22half2_rn(make_float2(acc[ri].z, acc[ri].w));
        __half2* dst = (__half2*)(g_WhH + ((size_t)r * N + grow) * H0 + cgp * 4);
        dst[0] = h01;
        dst[1] = h23;
        float ps = acc[ri].x * av.x + acc[ri].y * av.y + acc[ri].z * av.z + acc[ri].w * av.w;
        float pd = acc[ri].x * ad.x + acc[ri].y * ad.y + acc[ri].z * ad.z + acc[ri].w * ad.w;
#pragma unroll
        for (int off = 8; off > 0; off >>= 1) {
            ps += __shfl_down_sync(0xffffffffu, ps, off, 16);
            pd += __shfl_down_sync(0xffffffffu, pd, off, 16);
        }
        if (cgp == 0) { g_ssrc[r * N + grow] = ps; g_sdst[r * N + grow] = pd; }
    }
}

// == kernel 2: 3-relation scan + softmax + gather + sigmoid-fuse + support ==
__global__ void __launch_bounds__(256)
scan_attn_fuse_kernel(const float* __restrict__ adj,
                      const void* __restrict__ relation,
                      const float* __restrict__ Wg0) {
    __shared__ int      s_idx[3][CAP];
    __shared__ float    s_w[3][CAP];
    __shared__ unsigned long long s_wsum[8];
    __shared__ float    s_m[3][8];
    __shared__ float    s_s[3][8];
    __shared__ float    s_acc[3][4][H0];
    __shared__ float    s_hp[H0];
    __shared__ float    s_part[4][H0];

    int i = blockIdx.x;
    int tid = threadIdx.x;
    int lane = tid & 31, wid = tid >> 5;

    const float4* r0p = (const float4*)(adj + (size_t)i * N);
    const float4* r1p = (const float4*)(adj + ((size_t)N + i) * N);
    const float4* r2p = (const float4*)(adj + ((size_t)2 * N + i) * N);
    unsigned m0, m1, m2;
    {
        float4 a0 = r0p[tid], a1v = r0p[tid + 256], a2v = r0p[tid + 512], a3v = r0p[tid + 768];
        float4 b0 = r1p[tid], b1v = r1p[tid + 256], b2v = r1p[tid + 512], b3v = r1p[tid + 768];
        float4 c0 = r2p[tid], c1v = r2p[tid + 256], c2v = r2p[tid + 512], c3v = r2p[tid + 768];
        m0 = mask16(a0, a1v, a2v, a3v);
        m1 = mask16(b0, b1v, b2v, b3v);
        m2 = mask16(c0, c1v, c2v, c3v);
    }
    unsigned long long pc = (unsigned long long)__popc(m0)
                          | ((unsigned long long)__popc(m1) << 21)
                          | ((unsigned long long)__popc(m2) << 42);

    unsigned long long pre = pc;
#pragma unroll
    for (int off = 1; off < 32; off <<= 1) {
        unsigned long long nv = __shfl_up_sync(0xffffffffu, pre, off);
        if (lane >= off) pre += nv;
    }
    if (lane == 31) s_wsum[wid] = pre;
    __syncthreads();
    unsigned long long wbase = 0, totp = 0;
#pragma unroll
    for (int w = 0; w < 8; w++) {
        unsigned long long v = s_wsum[w];
        if (w < wid) wbase += v;
        totp += v;
    }
    unsigned long long startp = wbase + pre - pc;
    int pos[3], total[3], cnt[3];
    unsigned msk[3] = {m0, m1, m2};
#pragma unroll
    for (int r = 0; r < 3; r++) {
        pos[r]   = (int)((startp >> (21 * r)) & 0x1FFFFFull);
        total[r] = (int)((totp   >> (21 * r)) & 0x1FFFFFull);
        cnt[r]   = min(total[r], CAP);
    }

#pragma unroll
    for (int r = 0; r < 3; r++) {
        unsigned mm = msk[r];
        int p = pos[r];
        while (mm) {
            int bb = __ffs(mm) - 1;
            mm &= mm - 1;
            int q = bb >> 2, j = bb & 3;
            int col = ((tid + (q << 8)) << 2) + j;
            if (p < CAP) s_idx[r][p] = col;
            p++;
        }
    }
    __syncthreads();

    int relv = read_relation(relation);
    {
        int* gl = g_nbr_idx + (size_t)i * CAP;
        int c = cnt[relv];
        const int* src = s_idx[relv];
        for (int k = tid; k < c; k += 256) gl[k] = src[k];
        if (tid == 0) g_nbr_cnt[i] = total[relv];
    }

    float sc[3];
#pragma unroll
    for (int r = 0; r < 3; r++) {
        float si = g_ssrc[r * N + i];
        sc[r] = (tid < cnt[r]) ? leaky(si + g_sdst[r * N + s_idx[r][tid]]) : -FLT_MAX;
    }
    float mm[3] = {sc[0], sc[1], sc[2]};
#pragma unroll
    for (int off = 16; off > 0; off >>= 1) {
        mm[0] = fmaxf(mm[0], __shfl_xor_sync(0xffffffffu, mm[0], off));
        mm[1] = fmaxf(mm[1], __shfl_xor_sync(0xffffffffu, mm[1], off));
        mm[2] = fmaxf(mm[2], __shfl_xor_sync(0xffffffffu, mm[2], off));
    }
    if (lane == 0) { s_m[0][wid] = mm[0]; s_m[1][wid] = mm[1]; s_m[2][wid] = mm[2]; }
    __syncthreads();
    float bm[3] = {s_m[0][0], s_m[1][0], s_m[2][0]};
#pragma unroll
    for (int w = 1; w < 8; w++) {
        bm[0] = fmaxf(bm[0], s_m[0][w]);
        bm[1] = fmaxf(bm[1], s_m[1][w]);
        bm[2] = fmaxf(bm[2], s_m[2][w]);
    }
    float su[3];
#pragma unroll
    for (int r = 0; r < 3; r++) {
        float e = (tid < cnt[r]) ? __expf(sc[r] - bm[r]) : 0.f;
        s_w[r][tid] = e;
        su[r] = e;
    }
#pragma unroll
    for (int off = 16; off > 0; off >>= 1) {
        su[0] += __shfl_xor_sync(0xffffffffu, su[0], off);
        su[1] += __shfl_xor_sync(0xffffffffu, su[1], off);
        su[2] += __shfl_xor_sync(0xffffffffu, su[2], off);
    }
    if (lane == 0) { s_s[0][wid] = su[0]; s_s[1][wid] = su[1]; s_s[2][wid] = su[2]; }
    __syncthreads();
    float inv[3];
#pragma unroll
    for (int r = 0; r < 3; r++) {
        float bs = s_s[r][0];
#pragma unroll
        for (int w = 1; w < 8; w++) bs += s_s[r][w];
        inv[r] = 1.f / bs;
    }

    // --- weighted gathers: MLP8 main loop + clamped-index zero-weight tail
    int f = tid & 63;
    int kc = tid >> 6;
#pragma unroll
    for (int r = 0; r < 3; r++) {
        const __half* WhR = g_WhH + (size_t)r * N * H0;
        float acc = 0.f;
        int c = cnt[r];
        int k = kc;
        for (; k + 28 < c; k += 32) {
            int j0 = s_idx[r][k],      j1 = s_idx[r][k + 4],  j2 = s_idx[r][k + 8],  j3 = s_idx[r][k + 12];
            int j4 = s_idx[r][k + 16], j5 = s_idx[r][k + 20], j6 = s_idx[r][k + 24], j7 = s_idx[r][k + 28];
            float w0 = s_w[r][k],      w1 = s_w[r][k + 4],  w2 = s_w[r][k + 8],  w3 = s_w[r][k + 12];
            float w4 = s_w[r][k + 16], w5 = s_w[r][k + 20], w6 = s_w[r][k + 24], w7 = s_w[r][k + 28];
            float p0 = __half2float(WhR[(size_t)j0 * H0 + f]);
            float p1 = __half2float(WhR[(size_t)j1 * H0 + f]);
            float p2 = __half2float(WhR[(size_t)j2 * H0 + f]);
            float p3 = __half2float(WhR[(size_t)j3 * H0 + f]);
            float p4 = __half2float(WhR[(size_t)j4 * H0 + f]);
            float p5 = __half2float(WhR[(size_t)j5 * H0 + f]);
            float p6 = __half2float(WhR[(size_t)j6 * H0 + f]);
            float p7 = __half2float(WhR[(size_t)j7 * H0 + f]);
            acc = fmaf(w0, p0, acc); acc = fmaf(w1, p1, acc);
            acc = fmaf(w2, p2, acc); acc = fmaf(w3, p3, acc);
            acc = fmaf(w4, p4, acc); acc = fmaf(w5, p5, acc);
            acc = fmaf(w6, p6, acc); acc = fmaf(w7, p7, acc);
        }
        if (k < c) {
            int cm = c - 1;   // c >= 1 (self-loop) so cm >= 0; all reads in-bounds
#pragma unroll
            for (int t = 0; t < 8; t++) {
                int kk = k + 4 * t;
                int kcl = min(kk, cm);
                int jt = s_idx[r][kcl];
                float wv = s_w[r][kcl];
                float wt = (kk < c) ? wv : 0.f;
                acc = fmaf(wt, __half2float(WhR[(size_t)jt * H0 + f]), acc);
            }
        }
        s_acc[r][kc][f] = acc;
    }
    __syncthreads();

    if (tid < H0) {
        float h0 = (s_acc[0][0][tid] + s_acc[0][1][tid] + s_acc[0][2][tid] + s_acc[0][3][tid]) * inv[0];
        float h1 = (s_acc[1][0][tid] + s_acc[1][1][tid] + s_acc[1][2][tid] + s_acc[1][3][tid]) * inv[1];
        float h2 = (s_acc[2][0][tid] + s_acc[2][1][tid] + s_acc[2][2][tid] + s_acc[2][3][tid]) * inv[2];
        float v = (h0 + h1 + h2) * (1.f / 3.f);
        s_hp[tid] = 1.f / (1.f + __expf(-v));
    }
    __syncthreads();

    {
        float partial = 0.f;
        int kbeg = kc * 16;
#pragma unroll 16
        for (int k = 0; k < 16; k++)
            partial = fmaf(s_hp[kbeg + k], Wg0[(kbeg + k) * H1 + f], partial);
        s_part[kc][f] = partial;
    }
    __syncthreads();
    if (tid < H0) {
        g_support[(size_t)i * H1 + tid] =
            s_part[0][tid] + s_part[1][tid] + s_part[2][tid] + s_part[3][tid];
    }
}

// ================= kernel 3: gnn layer 1 (warp/row, MLP=8, smem weights) ===
__global__ void __launch_bounds__(256)
gnn1_kernel(const float* __restrict__ bg0,
            const float* __restrict__ br) {
    __shared__ int    sidx[8][CAP];
    __shared__ float  shp[8][H1];
    __shared__ float2 scw[H1 * H2];
    int tid = threadIdx.x;
    int lane = tid & 31, wid = tid >> 5;
    int i = blockIdx.x * 8 + wid;

    {
        const float4* src = (const float4*)g_WgC;
        float4* dst = (float4*)scw;
#pragma unroll
        for (int q = 0; q < 4; q++) dst[tid + q * 256] = src[tid + q * 256];
    }

    int total = g_nbr_cnt[i];
    int cnt = min(total, CAP);
    const int* gl = g_nbr_idx + (size_t)i * CAP;
    for (int k = lane; k < cnt; k += 32) sidx[wid][k] = gl[k];
    __syncwarp();

    const float2* sup = (const float2*)g_support;
    float2 a0 = {0.f, 0.f}, a1 = {0.f, 0.f}, a2 = {0.f, 0.f}, a3 = {0.f, 0.f};
    float2 a4 = {0.f, 0.f}, a5 = {0.f, 0.f}, a6 = {0.f, 0.f}, a7 = {0.f, 0.f};
    int k = 0;
    for (; k + 8 <= cnt; k += 8) {
        int4 j0 = *(const int4*)&sidx[wid][k];
        int4 j1 = *(const int4*)&sidx[wid][k + 4];
        float2 p0 = sup[(size_t)j0.x * 32 + lane];
        float2 p1 = sup[(size_t)j0.y * 32 + lane];
        float2 p2 = sup[(size_t)j0.z * 32 + lane];
        float2 p3 = sup[(size_t)j0.w * 32 + lane];
        float2 p4 = sup[(size_t)j1.x * 32 + lane];
        float2 p5 = sup[(size_t)j1.y * 32 + lane];
        float2 p6 = sup[(size_t)j1.z * 32 + lane];
        float2 p7 = sup[(size_t)j1.w * 32 + lane];
        a0.x += p0.x; a0.y += p0.y;  a1.x += p1.x; a1.y += p1.y;
        a2.x += p2.x; a2.y += p2.y;  a3.x += p3.x; a3.y += p3.y;
        a4.x += p4.x; a4.y += p4.y;  a5.x += p5.x; a5.y += p5.y;
        a6.x += p6.x; a6.y += p6.y;  a7.x += p7.x; a7.y += p7.y;
    }
    if (k < cnt) {
        int cm = cnt - 1;  // cnt >= 1 (self-loop); clamped reads in-bounds
#pragma unroll
        for (int t = 0; t < 8; t++) {
            int kk = k + t;
            int jt = sidx[wid][min(kk, cm)];
            float2 p = sup[(size_t)jt * 32 + lane];
            if (kk < cnt) { a0.x += p.x; a0.y += p.y; }
        }
    }
    float dinv = 1.f / (float)total;
    float2 bg = ((const float2*)bg0)[lane];
    float2 h;
    h.x = leaky((a0.x + a1.x + a2.x + a3.x + a4.x + a5.x + a6.x + a7.x) * dinv + bg.x);
    h.y = leaky((a0.y + a1.y + a2.y + a3.y + a4.y + a5.y + a6.y + a7.y) * dinv + bg.y);
    *(float2*)&shp[wid][2 * lane] = h;
    __syncthreads();

    float s2 = 0.f, rr2 = 0.f;
#pragma unroll
    for (int kk = 0; kk < H1; kk += 4) {
        float4 hv = *(const float4*)&shp[wid][kk];
        float2 w0 = scw[(kk + 0) * H2 + lane];
        float2 w1 = scw[(kk + 1) * H2 + lane];
        float2 w2 = scw[(kk + 2) * H2 + lane];
        float2 w3 = scw[(kk + 3) * H2 + lane];
        s2  = fmaf(hv.x, w0.x, s2);  rr2 = fmaf(hv.x, w0.y, rr2);
        s2  = fmaf(hv.y, w1.x, s2);  rr2 = fmaf(hv.y, w1.y, rr2);
        s2  = fmaf(hv.z, w2.x, s2);  rr2 = fmaf(hv.z, w2.y, rr2);
        s2  = fmaf(hv.w, w3.x, s2);  rr2 = fmaf(hv.w, w3.y, rr2);
    }
    g_support2[(size_t)i * H2 + lane] = s2;
    g_resid[(size_t)i * H2 + lane]    = rr2 + br[lane];
}

// ================= kernel 4: gnn layer 2 + residual -> out (MLP=16) =======
__global__ void __launch_bounds__(256)
gnn2_kernel(const float* __restrict__ bg1,
            float* __restrict__ out) {
    __shared__ int sidx[8][CAP];
    int tid = threadIdx.x;
    int lane = tid & 31, wid = tid >> 5;
    int i = blockIdx.x * 8 + wid;
    int total = g_nbr_cnt[i];
    int cnt = min(total, CAP);
    const int* gl = g_nbr_idx + (size_t)i * CAP;
    for (int k = lane; k < cnt; k += 32) sidx[wid][k] = gl[k];
    __syncwarp();

    const float* sup2 = g_support2;
    float a0 = 0.f, a1 = 0.f, a2 = 0.f, a3 = 0.f;
    float a4 = 0.f, a5 = 0.f, a6 = 0.f, a7 = 0.f;
    float b0 = 0.f, b1 = 0.f, b2 = 0.f, b3 = 0.f;
    float b4 = 0.f, b5 = 0.f, b6 = 0.f, b7 = 0.f;
    int k = 0;
    for (; k + 16 <= cnt; k += 16) {
        int4 j0 = *(const int4*)&sidx[wid][k];
        int4 j1 = *(const int4*)&sidx[wid][k + 4];
        int4 j2 = *(const int4*)&sidx[wid][k + 8];
        int4 j3 = *(const int4*)&sidx[wid][k + 12];
        a0 += sup2[(size_t)j0.x * H2 + lane];
        a1 += sup2[(size_t)j0.y * H2 + lane];
        a2 += sup2[(size_t)j0.z * H2 + lane];
        a3 += sup2[(size_t)j0.w * H2 + lane];
        a4 += sup2[(size_t)j1.x * H2 + lane];
        a5 += sup2[(size_t)j1.y * H2 + lane];
        a6 += sup2[(size_t)j1.z * H2 + lane];
        a7 += sup2[(size_t)j1.w * H2 + lane];
        b0 += sup2[(size_t)j2.x * H2 + lane];
        b1 += sup2[(size_t)j2.y * H2 + lane];
        b2 += sup2[(size_t)j2.z * H2 + lane];
        b3 += sup2[(size_t)j2.w * H2 + lane];
        b4 += sup2[(size_t)j3.x * H2 + lane];
        b5 += sup2[(size_t)j3.y * H2 + lane];
        b6 += sup2[(size_t)j3.z * H2 + lane];
        b7 += sup2[(size_t)j3.w * H2 + lane];
    }
    if (k < cnt) {
        int cm = cnt - 1;  // clamped reads in-bounds; adds predicated
#pragma unroll
        for (int t = 0; t < 16; t++) {
            int kk = k + t;
            int jt = sidx[wid][min(kk, cm)];
            float v = sup2[(size_t)jt * H2 + lane];
            if (kk < cnt) {
                if (t < 8) { if ((t & 3) == 0) a0 += v; else if ((t & 3) == 1) a1 += v; else if ((t & 3) == 2) a2 += v; else a3 += v; }
                else       { if ((t & 3) == 0) b0 += v; else if ((t & 3) == 1) b1 += v; else if ((t & 3) == 2) b2 += v; else b3 += v; }
            }
        }
    }
    float agg = (a0 + a1 + a2 + a3 + a4 + a5 + a6 + a7)
              + (b0 + b1 + b2 + b3 + b4 + b5 + b6 + b7);
    float v = leaky(agg * (1.f / (float)total) + bg1[lane]);
    out[(size_t)i * H2 + lane] = v + g_resid[(size_t)i * H2 + lane];
}

extern "C" void kernel_launch(void* const* d_in, const int* in_sizes, int n_in,
                              void* d_out, int out_size) {
    const float* x   = (const float*)d_in[0];
    const float* adj = (const float*)d_in[1];
    const float* W1  = (const float*)d_in[2];
    const float* a1  = (const float*)d_in[3];
    const float* W2  = (const float*)d_in[4];
    const float* a2  = (const float*)d_in[5];
    const float* W3  = (const float*)d_in[6];
    const float* a3  = (const float*)d_in[7];
    const float* Wg0 = (const float*)d_in[8];
    const float* bg0 = (const float*)d_in[9];
    const float* Wg1 = (const float*)d_in[10];
    const float* bg1 = (const float*)d_in[11];
    const float* Wr  = (const float*)d_in[12];
    const float* br  = (const float*)d_in[13];
    const void*  rel = d_in[14];
    float* out = (float*)d_out;

    wh_kernel<<<dim3(128, 3), 256>>>(x, W1, a1, W2, a2, W3, a3, Wg1, Wr);
    scan_attn_fuse_kernel<<<N, 256>>>(adj, rel, Wg0);
    gnn1_kernel<<<N / 8, 256>>>(bg0, br);
    gnn2_kernel<<<N / 8, 256>>>(bg1, out);
}